// round 8
// baseline (speedup 1.0000x reference)
#include <cuda_runtime.h>
#include <math.h>

#define B_   2
#define S_   2048
#define H_   1024
#define NH_  16
#define HD_  64
#define WIN_ 1024

// ---------------- scratch (device globals: no allocations allowed) ----------
__device__ float g_q[B_*NH_*S_*HD_];
__device__ float g_k[B_*NH_*S_*HD_];
__device__ float g_v[B_*NH_*S_*HD_];
__device__ float g_ctx[B_*S_*H_];

// ---------------- SGEMM: Y[m,n] = sum_k X[m,k] * W[n,k] + bias[n] -----------
// 128x128 tile, 8-deep K panels, double-buffered smem (one barrier/panel).
// MODE 0: X = hidden_states, blockIdx.z selects (Wq,Wk,Wv), epilogue scatters
//         into g_q/g_k/g_v with [B, NH, S, HD] layout.
// MODE 1: X = g_ctx, W = Wo, writes directly to OUT [4096, 1024].
template<int MODE>
__global__ __launch_bounds__(256)
void sgemm_kernel(const float* __restrict__ X,
                  const float* __restrict__ W0, const float* __restrict__ Bi0,
                  const float* __restrict__ W1, const float* __restrict__ Bi1,
                  const float* __restrict__ W2, const float* __restrict__ Bi2,
                  float* __restrict__ OUT)
{
    __shared__ float As[2][8][132];   // padded: conflict-free transposed stores
    __shared__ float Bs[2][8][132];

    const int tid = threadIdx.x;
    const int tn  = tid & 15;
    const int tm  = tid >> 4;
    const int m0  = blockIdx.y * 128;
    const int n0  = blockIdx.x * 128;
    const int z   = (MODE == 0) ? (int)blockIdx.z : 0;

    const float* W  = W0;
    const float* Bi = Bi0;
    if (MODE == 0) {
        if (z == 1) { W = W1; Bi = Bi1; }
        else if (z == 2) { W = W2; Bi = Bi2; }
    }
    const float* Xp = (MODE == 0) ? X : g_ctx;

    const int arow = tid >> 1;        // 0..127
    const int ak   = (tid & 1) << 2;  // 0 or 4

    float acc[8][8];
    #pragma unroll
    for (int i = 0; i < 8; i++)
        #pragma unroll
        for (int j = 0; j < 8; j++) acc[i][j] = 0.f;

    const float* Aptr = Xp + (size_t)(m0 + arow) * 1024 + ak;
    const float* Bptr = W  + (size_t)(n0 + arow) * 1024 + ak;

    // prologue: load panel 0 into buffer 0
    {
        float4 av = *(const float4*)(Aptr);
        float4 bv = *(const float4*)(Bptr);
        As[0][ak+0][arow] = av.x; As[0][ak+1][arow] = av.y;
        As[0][ak+2][arow] = av.z; As[0][ak+3][arow] = av.w;
        Bs[0][ak+0][arow] = bv.x; Bs[0][ak+1][arow] = bv.y;
        Bs[0][ak+2][arow] = bv.z; Bs[0][ak+3][arow] = bv.w;
    }
    __syncthreads();

    int cur = 0;
    for (int k0 = 0; k0 < 1024; k0 += 8) {
        float4 av, bv;
        const bool more = (k0 + 8) < 1024;
        if (more) {
            av = *(const float4*)(Aptr + k0 + 8);
            bv = *(const float4*)(Bptr + k0 + 8);
        }

        #pragma unroll
        for (int kk = 0; kk < 8; kk++) {
            float a[8], b[8];
            #pragma unroll
            for (int i = 0; i < 8; i++) a[i] = As[cur][kk][tm*8 + i];
            #pragma unroll
            for (int j = 0; j < 8; j++) b[j] = Bs[cur][kk][tn*8 + j];
            #pragma unroll
            for (int i = 0; i < 8; i++)
                #pragma unroll
                for (int j = 0; j < 8; j++)
                    acc[i][j] = fmaf(a[i], b[j], acc[i][j]);
        }

        if (more) {
            const int nxt = cur ^ 1;
            As[nxt][ak+0][arow] = av.x; As[nxt][ak+1][arow] = av.y;
            As[nxt][ak+2][arow] = av.z; As[nxt][ak+3][arow] = av.w;
            Bs[nxt][ak+0][arow] = bv.x; Bs[nxt][ak+1][arow] = bv.y;
            Bs[nxt][ak+2][arow] = bv.z; Bs[nxt][ak+3][arow] = bv.w;
            __syncthreads();
            cur = nxt;
        }
    }

    #pragma unroll
    for (int i = 0; i < 8; i++) {
        const int m = m0 + tm*8 + i;
        #pragma unroll
        for (int j = 0; j < 8; j++) {
            const int n = n0 + tn*8 + j;
            const float v = acc[i][j] + Bi[n];
            if (MODE == 0) {
                const int b = m >> 11;          // m / S_
                const int s = m & (S_ - 1);
                const int h = n >> 6;           // n / HD_
                const int d = n & 63;
                float* dst = (z == 0) ? g_q : (z == 1) ? g_k : g_v;
                dst[(((size_t)b*NH_ + h)*S_ + s)*HD_ + d] = v;
            } else {
                OUT[(size_t)m * H_ + n] = v;
            }
        }
    }
}

// ---------------- RoPE (in-place on g_q / g_k) ------------------------------
// position_ids dtype robustness: the reference declares int64 but JAX with
// x64 disabled (the default) downcasts to int32. For the arange input, the
// int32 view of an int64 little-endian arange is 0,0,1,0,2,0,... so
// (i32[1]==0 && i32[2]==1 && i32[3]==0) identifies int64 storage; we then
// read the low word at 2*idx. Otherwise read int32 directly. Deterministic.
__global__ void rope_kernel(const int* __restrict__ pos32)
{
    const int idx = blockIdx.x * blockDim.x + threadIdx.x;
    if (idx >= B_*NH_*S_*(HD_/2)) return;
    const int d  = idx & 31;
    const int t  = idx >> 5;
    const int s  = t & (S_ - 1);
    const int t2 = t >> 11;
    const int h  = t2 & (NH_ - 1);
    const int b  = t2 >> 4;

    const bool is64 = (pos32[1] == 0) && (pos32[2] == 1) && (pos32[3] == 0);
    const int pidx = b*S_ + s;
    int p = is64 ? pos32[2*pidx] : pos32[pidx];
    if (p < 0) p = 0;
    if (p > 2047) p = 2047;

    // inv_freq[d] = 10000^(-d/32) = exp(-ln(10000)/32 * d)
    const float inv = expf(-0.28782313662425575f * (float)d);
    const float ang = (float)p * inv;
    float sn, cs;
    sincosf(ang, &sn, &cs);

    const size_t base = (((size_t)b*NH_ + h)*S_ + s)*HD_;
    const float q1 = g_q[base + d], q2 = g_q[base + d + 32];
    g_q[base + d]      = q1*cs - q2*sn;
    g_q[base + d + 32] = q2*cs + q1*sn;
    const float k1 = g_k[base + d], k2 = g_k[base + d + 32];
    g_k[base + d]      = k1*cs - k2*sn;
    g_k[base + d + 32] = k2*cs + k1*sn;
}

// ---------------- Flash attention with sliding window -----------------------
// Block = (q-tile 64, head, batch). 256 threads as 16x16; each thread owns a
// 4x4 micro-tile of the 64x64 score / output tiles. Online softmax.
#define ALD 68   // padded leading dim for 64-wide tiles
#define ATT_SMEM_FLOATS (4*64*ALD + 64*17 + 4*64)
#define ATT_SMEM_BYTES  (ATT_SMEM_FLOATS * 4)

__global__ __launch_bounds__(256)
void attn_kernel()
{
    extern __shared__ float sm[];
    float* Qs        = sm;                  // 64 x ALD
    float* Ks        = Qs + 64*ALD;
    float* Vs        = Ks + 64*ALD;
    float* Ps        = Vs + 64*ALD;
    float* red       = Ps + 64*ALD;         // 64 x 17
    float* row_m     = red + 64*17;
    float* row_l     = row_m + 64;
    float* row_scale = row_l + 64;
    float* row_mnew  = row_scale + 64;

    const int tid = threadIdx.x;
    const int tx  = tid & 15;
    const int ty  = tid >> 4;
    const int qi  = blockIdx.x;
    const int h   = blockIdx.y;
    const int b   = blockIdx.z;
    const int q0  = qi * 64;

    const float* Qg = g_q + (((size_t)b*NH_ + h)*S_ + q0)*HD_;
    const float* Kg = g_k + (((size_t)b*NH_ + h)*S_)*HD_;
    const float* Vg = g_v + (((size_t)b*NH_ + h)*S_)*HD_;

    // load Q tile (64x64)
    #pragma unroll
    for (int t = 0; t < 4; t++) {
        const int l  = t*256 + tid;
        const int r  = l >> 4;
        const int c4 = (l & 15) << 2;
        *(float4*)(Qs + r*ALD + c4) = *(const float4*)(Qg + r*64 + c4);
    }
    if (tid < 64) { row_m[tid] = -1e30f; row_l[tid] = 0.f; }

    float acc[4][4];
    #pragma unroll
    for (int i = 0; i < 4; i++)
        #pragma unroll
        for (int j = 0; j < 4; j++) acc[i][j] = 0.f;

    int j0 = qi - 16; if (j0 < 0) j0 = 0;   // window tail block is partial
    __syncthreads();

    for (int j = j0; j <= qi; j++) {
        const int k0 = j * 64;
        // load K,V tiles
        #pragma unroll
        for (int t = 0; t < 4; t++) {
            const int l  = t*256 + tid;
            const int r  = l >> 4;
            const int c4 = (l & 15) << 2;
            *(float4*)(Ks + r*ALD + c4) = *(const float4*)(Kg + (size_t)(k0+r)*64 + c4);
            *(float4*)(Vs + r*ALD + c4) = *(const float4*)(Vg + (size_t)(k0+r)*64 + c4);
        }
        __syncthreads();

        // S = Q K^T * 0.125
        float s[4][4];
        #pragma unroll
        for (int i = 0; i < 4; i++)
            #pragma unroll
            for (int jj = 0; jj < 4; jj++) s[i][jj] = 0.f;
        #pragma unroll 8
        for (int kk = 0; kk < 64; kk++) {
            float a[4], bb[4];
            #pragma unroll
            for (int i = 0; i < 4; i++)  a[i]  = Qs[(ty*4+i)*ALD + kk];
            #pragma unroll
            for (int jj = 0; jj < 4; jj++) bb[jj] = Ks[(tx*4+jj)*ALD + kk];
            #pragma unroll
            for (int i = 0; i < 4; i++)
                #pragma unroll
                for (int jj = 0; jj < 4; jj++)
                    s[i][jj] = fmaf(a[i], bb[jj], s[i][jj]);
        }

        // scale + mask + partial row max
        #pragma unroll
        for (int i = 0; i < 4; i++) {
            const int qg = q0 + ty*4 + i;
            float pm = -1e30f;
            #pragma unroll
            for (int jj = 0; jj < 4; jj++) {
                const int kg = k0 + tx*4 + jj;
                float v = s[i][jj] * 0.125f;
                if (kg > qg || qg - kg >= WIN_) v = -1e30f;
                s[i][jj] = v;
                pm = fmaxf(pm, v);
            }
            red[(ty*4+i)*17 + tx] = pm;
        }
        __syncthreads();

        if (tid < 64) {
            const float m_old = row_m[tid];
            float mx = m_old;
            #pragma unroll
            for (int t = 0; t < 16; t++) mx = fmaxf(mx, red[tid*17 + t]);
            row_mnew[tid]  = mx;
            row_m[tid]     = mx;
            row_scale[tid] = __expf(m_old - mx);
        }
        __syncthreads();

        // P = exp(S - m_new); rescale accumulators; partial row sums
        #pragma unroll
        for (int i = 0; i < 4; i++) {
            const int r  = ty*4 + i;
            const float mn = row_mnew[r];
            const float sc = row_scale[r];
            float ps = 0.f;
            #pragma unroll
            for (int jj = 0; jj < 4; jj++) {
                const float p = (s[i][jj] < -1e29f) ? 0.f : __expf(s[i][jj] - mn);
                Ps[r*ALD + tx*4 + jj] = p;
                ps += p;
                acc[i][jj] *= sc;
            }
            red[r*17 + tx] = ps;
        }
        __syncthreads();

        if (tid < 64) {
            float sum = 0.f;
            #pragma unroll
            for (int t = 0; t < 16; t++) sum += red[tid*17 + t];
            row_l[tid] = row_l[tid] * row_scale[tid] + sum;
        }

        // O += P V
        #pragma unroll 8
        for (int kk = 0; kk < 64; kk++) {
            float p[4], v[4];
            #pragma unroll
            for (int i = 0; i < 4; i++)  p[i] = Ps[(ty*4+i)*ALD + kk];
            #pragma unroll
            for (int jj = 0; jj < 4; jj++) v[jj] = Vs[kk*ALD + tx*4 + jj];
            #pragma unroll
            for (int i = 0; i < 4; i++)
                #pragma unroll
                for (int jj = 0; jj < 4; jj++)
                    acc[i][jj] = fmaf(p[i], v[jj], acc[i][jj]);
        }
        __syncthreads();   // protects Ks/Vs/red for next iter; publishes row_l
    }

    // normalize and write ctx in [B, S, H] layout
    float* ctx = g_ctx + ((size_t)b*S_ + q0)*H_ + h*HD_;
    #pragma unroll
    for (int i = 0; i < 4; i++) {
        const int r = ty*4 + i;
        const float invl = 1.f / row_l[r];
        #pragma unroll
        for (int jj = 0; jj < 4; jj++)
            ctx[(size_t)r*H_ + tx*4 + jj] = acc[i][jj] * invl;
    }
}

// ---------------- launch -----------------------------------------------------
extern "C" void kernel_launch(void* const* d_in, const int* in_sizes, int n_in,
                              void* d_out, int out_size)
{
    const float* x   = (const float*)d_in[0];
    const int*   pos = (const int*)d_in[1];    // int32 (JAX x64-off) or int64 (sniffed)
    const float* wq = (const float*)d_in[2];
    const float* bq = (const float*)d_in[3];
    const float* wk = (const float*)d_in[4];
    const float* bk = (const float*)d_in[5];
    const float* wv = (const float*)d_in[6];
    const float* bv = (const float*)d_in[7];
    const float* wo = (const float*)d_in[8];
    const float* bo = (const float*)d_in[9];
    float* out = (float*)d_out;

    cudaFuncSetAttribute(attn_kernel,
                         cudaFuncAttributeMaxDynamicSharedMemorySize,
                         ATT_SMEM_BYTES);

    dim3 gqkv(H_/128, (B_*S_)/128, 3);          // 8 x 32 x 3
    sgemm_kernel<0><<<gqkv, 256>>>(x, wq, bq, wk, bk, wv, bv, out);

    const int npairs = B_*NH_*S_*(HD_/2);
    rope_kernel<<<(npairs + 255)/256, 256>>>(pos);

    dim3 gatt(S_/64, NH_, B_);                  // 32 x 16 x 2
    attn_kernel<<<gatt, 256, ATT_SMEM_BYTES>>>();

    dim3 gout(H_/128, (B_*S_)/128, 1);          // 8 x 32
    sgemm_kernel<1><<<gout, 256>>>(x, wo, bo, nullptr, nullptr, nullptr, nullptr, out);
}

// round 11
// speedup vs baseline: 1.6602x; 1.6602x over previous
#include <cuda_runtime.h>
#include <cuda_bf16.h>
#include <math.h>
#include <stdint.h>

#define B_   2
#define S_   2048
#define H_   1024
#define NH_  16
#define HD_  64
#define WIN_ 1024

// ---------------- scratch (device globals: no allocations allowed) ----------
__device__ float g_q[B_*NH_*S_*HD_];
__device__ float g_k[B_*NH_*S_*HD_];
__device__ float g_v[B_*NH_*S_*HD_];
__device__ float g_ctx[B_*S_*H_];
// bf16 split operands
__device__ __nv_bfloat16 g_xh[B_*S_*H_];
__device__ __nv_bfloat16 g_xl[B_*S_*H_];
__device__ __nv_bfloat16 g_wh[4*H_*H_];
__device__ __nv_bfloat16 g_wl[4*H_*H_];
__device__ __nv_bfloat16 g_ch[B_*S_*H_];
__device__ __nv_bfloat16 g_cl[B_*S_*H_];

// ---------------- helpers (base-target instructions only) --------------------
__device__ __forceinline__ uint32_t smem_u32(const void* p) {
    uint32_t a;
    asm("{ .reg .u64 t; cvta.to.shared.u64 t, %1; cvt.u32.u64 %0, t; }"
        : "=r"(a) : "l"(p));
    return a;
}
__device__ __forceinline__ uint32_t swz(uint32_t o) { return o ^ ((o >> 3) & 0x70); }

__device__ __forceinline__ void cp16(uint32_t dst, const void* src) {
    asm volatile("cp.async.cg.shared.global [%0], [%1], 16;" :: "r"(dst), "l"(src));
}
#define CP_COMMIT() asm volatile("cp.async.commit_group;" ::: "memory")
#define CP_WAIT0()  asm volatile("cp.async.wait_group 0;" ::: "memory")

__device__ __forceinline__ void ldsm_x4(uint32_t& r0, uint32_t& r1,
                                        uint32_t& r2, uint32_t& r3, uint32_t a) {
    asm volatile("ldmatrix.sync.aligned.m8n8.x4.shared.b16 {%0,%1,%2,%3}, [%4];"
                 : "=r"(r0), "=r"(r1), "=r"(r2), "=r"(r3) : "r"(a));
}
__device__ __forceinline__ void mma16816(float* c, const uint32_t* a, const uint32_t* b) {
    asm volatile("mma.sync.aligned.m16n8k16.row.col.f32.bf16.bf16.f32 "
                 "{%0,%1,%2,%3}, {%4,%5,%6,%7}, {%8,%9}, {%0,%1,%2,%3};"
                 : "+f"(c[0]), "+f"(c[1]), "+f"(c[2]), "+f"(c[3])
                 : "r"(a[0]), "r"(a[1]), "r"(a[2]), "r"(a[3]), "r"(b[0]), "r"(b[1]));
}

// ---------------- conversion kernels ----------------------------------------
__global__ void convert_inputs_kernel(const float* __restrict__ X,
                                      const float* __restrict__ Wq,
                                      const float* __restrict__ Wk,
                                      const float* __restrict__ Wv,
                                      const float* __restrict__ Wo)
{
    const int i = blockIdx.x * 256 + threadIdx.x;
    float v; __nv_bfloat16 *dh, *dl; int off;
    if (i < (1 << 22)) { v = X[i]; dh = g_xh; dl = g_xl; off = i; }
    else {
        const int j = i - (1 << 22);
        const int w = j >> 20;
        const int e = j & ((1 << 20) - 1);
        const float* Ws = (w == 0) ? Wq : (w == 1) ? Wk : (w == 2) ? Wv : Wo;
        v = Ws[e]; dh = g_wh; dl = g_wl; off = (w << 20) + e;
    }
    const __nv_bfloat16 h = __float2bfloat16(v);
    dh[off] = h;
    dl[off] = __float2bfloat16(v - __bfloat162float(h));
}
__global__ void convert_ctx_kernel()
{
    const int i = blockIdx.x * 256 + threadIdx.x;
    const float v = g_ctx[i];
    const __nv_bfloat16 h = __float2bfloat16(v);
    g_ch[i] = h;
    g_cl[i] = __float2bfloat16(v - __bfloat162float(h));
}

// ---------------- warp-MMA GEMM: Y = X W^T + bias ----------------------------
// 128x128 tile, K=1024 in 16 chunks of 64 bf16 (128B rows, SW128 swizzle).
// 8 warps as 2(m64) x 4(n32). mma.sync m16n8k16 bf16, 2-way split (3 products).
// cp.async double-buffered. MODE 0: scatter q/k/v. MODE 1: write OUT.
#define GM_STAGE (4*16384)                 // Ah, Al, Bh, Bl regions
#define GM_SMEM  (2*GM_STAGE + 1024)

template<int MODE>
__global__ __launch_bounds__(256, 1)
void mma_gemm(const float* __restrict__ bq, const float* __restrict__ bk,
              const float* __restrict__ bv, const float* __restrict__ bo,
              float* __restrict__ OUT)
{
    extern __shared__ char smem[];
    const uint32_t sb = smem_u32(smem);
    const uint32_t tile0 = (sb + 1023) & ~1023u;
    const int tid = threadIdx.x, wid = tid >> 5, lid = tid & 31;
    const int wm = wid & 1, wn = wid >> 1;
    const int n0 = blockIdx.x * 128, m0 = blockIdx.y * 128;
    const int z = (MODE == 0) ? (int)blockIdx.z : 3;

    const __nv_bfloat16* Ah = (MODE == 0) ? g_xh : g_ch;
    const __nv_bfloat16* Al = (MODE == 0) ? g_xl : g_cl;
    const __nv_bfloat16* Bh = g_wh + ((size_t)z << 20);
    const __nv_bfloat16* Bl = g_wl + ((size_t)z << 20);
    const float* Bi = (MODE == 0) ? ((z == 0) ? bq : (z == 1) ? bk : bv) : bo;

    const uint32_t stg[2] = { tile0, tile0 + GM_STAGE };

    float acc[4][4][4];
    #pragma unroll
    for (int i = 0; i < 4; i++)
        #pragma unroll
        for (int j = 0; j < 4; j++)
            #pragma unroll
            for (int r = 0; r < 4; r++) acc[i][j][r] = 0.f;

    // cp.async chunk loader: 4 regions x 128 rows x 128B
    auto load_chunk = [&](int kc, int buf) {
        const int koff = kc * 64;
        #pragma unroll
        for (int t = 0; t < 16; t++) {
            const int piece  = tid + t * 256;
            const int region = piece >> 10;          // 0:Ah 1:Al 2:Bh 3:Bl
            const int rem    = piece & 1023;
            const int row    = rem >> 3;
            const int c16    = rem & 7;
            const uint32_t dst = stg[buf] + region * 16384 + swz(row * 128 + c16 * 16);
            const __nv_bfloat16* src;
            if      (region == 0) src = Ah + (size_t)(m0 + row) * 1024 + koff + c16 * 8;
            else if (region == 1) src = Al + (size_t)(m0 + row) * 1024 + koff + c16 * 8;
            else if (region == 2) src = Bh + (size_t)(n0 + row) * 1024 + koff + c16 * 8;
            else                  src = Bl + (size_t)(n0 + row) * 1024 + koff + c16 * 8;
            cp16(dst, src);
        }
        CP_COMMIT();
    };

    // ldmatrix lane offsets (within a region, swizzled)
    const int a_row = lid & 15, a_k16 = lid >> 4;             // A: rows 0..15, k-half
    const int b_row = (lid & 7) + ((lid >> 4) & 1) * 8;       // B: n within 16
    const int b_k16 = (lid >> 3) & 1;

    load_chunk(0, 0);

    for (int c = 0; c < 16; c++) {
        const int cur = c & 1;
        CP_WAIT0();
        __syncthreads();
        if (c + 1 < 16) load_chunk(c + 1, cur ^ 1);

        const uint32_t ahB = stg[cur];
        const uint32_t alB = stg[cur] + 16384;
        const uint32_t bhB = stg[cur] + 32768;
        const uint32_t blB = stg[cur] + 49152;

        #pragma unroll
        for (int s = 0; s < 4; s++) {
            uint32_t ah[4][4], al[4][4], bh[2][4], bl[2][4];
            #pragma unroll
            for (int mf = 0; mf < 4; mf++) {
                const uint32_t off = swz((wm*64 + mf*16 + a_row) * 128 + s*32 + a_k16*16);
                ldsm_x4(ah[mf][0], ah[mf][1], ah[mf][2], ah[mf][3], ahB + off);
                ldsm_x4(al[mf][0], al[mf][1], al[mf][2], al[mf][3], alB + off);
            }
            #pragma unroll
            for (int np = 0; np < 2; np++) {
                const uint32_t off = swz((wn*32 + np*16 + b_row) * 128 + s*32 + b_k16*16);
                ldsm_x4(bh[np][0], bh[np][1], bh[np][2], bh[np][3], bhB + off);
                ldsm_x4(bl[np][0], bl[np][1], bl[np][2], bl[np][3], blB + off);
            }
            #pragma unroll
            for (int mf = 0; mf < 4; mf++)
                #pragma unroll
                for (int nf = 0; nf < 4; nf++) {
                    const uint32_t* bhf = &bh[nf >> 1][(nf & 1) * 2];
                    const uint32_t* blf = &bl[nf >> 1][(nf & 1) * 2];
                    mma16816(acc[mf][nf], ah[mf], bhf);
                    mma16816(acc[mf][nf], ah[mf], blf);
                    mma16816(acc[mf][nf], al[mf], bhf);
                }
        }
        __syncthreads();
    }

    // epilogue: c-frag lane mapping: row = l>>2 (+8 for c2,c3), col = 2*(l&3)+{0,1}
    const int erow = lid >> 2, ecol = (lid & 3) * 2;
    #pragma unroll
    for (int mf = 0; mf < 4; mf++) {
        #pragma unroll
        for (int nf = 0; nf < 4; nf++) {
            const int n  = n0 + wn*32 + nf*8 + ecol;
            const float bias0 = Bi[n], bias1 = Bi[n + 1];
            #pragma unroll
            for (int half = 0; half < 2; half++) {
                const int m = m0 + wm*64 + mf*16 + erow + half*8;
                const float v0 = acc[mf][nf][half*2 + 0] + bias0;
                const float v1 = acc[mf][nf][half*2 + 1] + bias1;
                if (MODE == 0) {
                    const int b = m >> 11;
                    const int s = m & (S_ - 1);
                    const int h = n >> 6;
                    const int d = n & 63;
                    float* dst = ((z == 0) ? g_q : (z == 1) ? g_k : g_v)
                               + (((size_t)b * NH_ + h) * S_ + s) * HD_ + d;
                    *(float2*)dst = make_float2(v0, v1);
                } else {
                    *(float2*)(OUT + (size_t)m * H_ + n) = make_float2(v0, v1);
                }
            }
        }
    }
}

// ---------------- RoPE (in-place on g_q / g_k) ------------------------------
__global__ void rope_kernel(const int* __restrict__ pos32)
{
    const int idx = blockIdx.x * blockDim.x + threadIdx.x;
    if (idx >= B_*NH_*S_*(HD_/2)) return;
    const int d  = idx & 31;
    const int t  = idx >> 5;
    const int s  = t & (S_ - 1);
    const int t2 = t >> 11;
    const int h  = t2 & (NH_ - 1);
    const int b  = t2 >> 4;

    const bool is64 = (pos32[1] == 0) && (pos32[2] == 1) && (pos32[3] == 0);
    const int pidx = b*S_ + s;
    int p = is64 ? pos32[2*pidx] : pos32[pidx];
    if (p < 0) p = 0;
    if (p > 2047) p = 2047;

    const float inv = expf(-0.28782313662425575f * (float)d);
    const float ang = (float)p * inv;
    float sn, cs;
    sincosf(ang, &sn, &cs);

    const size_t base = (((size_t)b*NH_ + h)*S_ + s)*HD_;
    const float q1 = g_q[base + d], q2 = g_q[base + d + 32];
    g_q[base + d]      = q1*cs - q2*sn;
    g_q[base + d + 32] = q2*cs + q1*sn;
    const float k1 = g_k[base + d], k2 = g_k[base + d + 32];
    g_k[base + d]      = k1*cs - k2*sn;
    g_k[base + d + 32] = k2*cs + k1*sn;
}

// ---------------- Flash attention with sliding window -----------------------
#define ALD 68
#define ATT_SMEM_FLOATS (4*64*ALD + 64*17 + 4*64)
#define ATT_SMEM_BYTES  (ATT_SMEM_FLOATS * 4)

__global__ __launch_bounds__(256)
void attn_kernel()
{
    extern __shared__ float sm[];
    float* Qs        = sm;
    float* Ks        = Qs + 64*ALD;
    float* Vs        = Ks + 64*ALD;
    float* Ps        = Vs + 64*ALD;
    float* red       = Ps + 64*ALD;
    float* row_m     = red + 64*17;
    float* row_l     = row_m + 64;
    float* row_scale = row_l + 64;
    float* row_mnew  = row_scale + 64;

    const int tid = threadIdx.x;
    const int tx  = tid & 15;
    const int ty  = tid >> 4;
    const int qi  = blockIdx.x;
    const int h   = blockIdx.y;
    const int b   = blockIdx.z;
    const int q0  = qi * 64;

    const float* Qg = g_q + (((size_t)b*NH_ + h)*S_ + q0)*HD_;
    const float* Kg = g_k + (((size_t)b*NH_ + h)*S_)*HD_;
    const float* Vg = g_v + (((size_t)b*NH_ + h)*S_)*HD_;

    #pragma unroll
    for (int t = 0; t < 4; t++) {
        const int l  = t*256 + tid;
        const int r  = l >> 4;
        const int c4 = (l & 15) << 2;
        *(float4*)(Qs + r*ALD + c4) = *(const float4*)(Qg + r*64 + c4);
    }
    if (tid < 64) { row_m[tid] = -1e30f; row_l[tid] = 0.f; }

    float acc[4][4];
    #pragma unroll
    for (int i = 0; i < 4; i++)
        #pragma unroll
        for (int j = 0; j < 4; j++) acc[i][j] = 0.f;

    int j0 = qi - 16; if (j0 < 0) j0 = 0;
    __syncthreads();

    for (int j = j0; j <= qi; j++) {
        const int k0 = j * 64;
        #pragma unroll
        for (int t = 0; t < 4; t++) {
            const int l  = t*256 + tid;
            const int r  = l >> 4;
            const int c4 = (l & 15) << 2;
            *(float4*)(Ks + r*ALD + c4) = *(const float4*)(Kg + (size_t)(k0+r)*64 + c4);
            *(float4*)(Vs + r*ALD + c4) = *(const float4*)(Vg + (size_t)(k0+r)*64 + c4);
        }
        __syncthreads();

        float s[4][4];
        #pragma unroll
        for (int i = 0; i < 4; i++)
            #pragma unroll
            for (int jj = 0; jj < 4; jj++) s[i][jj] = 0.f;
        #pragma unroll 8
        for (int kk = 0; kk < 64; kk++) {
            float a[4], bb[4];
            #pragma unroll
            for (int i = 0; i < 4; i++)  a[i]  = Qs[(ty*4+i)*ALD + kk];
            #pragma unroll
            for (int jj = 0; jj < 4; jj++) bb[jj] = Ks[(tx*4+jj)*ALD + kk];
            #pragma unroll
            for (int i = 0; i < 4; i++)
                #pragma unroll
                for (int jj = 0; jj < 4; jj++)
                    s[i][jj] = fmaf(a[i], bb[jj], s[i][jj]);
        }

        #pragma unroll
        for (int i = 0; i < 4; i++) {
            const int qg = q0 + ty*4 + i;
            float pm = -1e30f;
            #pragma unroll
            for (int jj = 0; jj < 4; jj++) {
                const int kg = k0 + tx*4 + jj;
                float v = s[i][jj] * 0.125f;
                if (kg > qg || qg - kg >= WIN_) v = -1e30f;
                s[i][jj] = v;
                pm = fmaxf(pm, v);
            }
            red[(ty*4+i)*17 + tx] = pm;
        }
        __syncthreads();

        if (tid < 64) {
            const float m_old = row_m[tid];
            float mx = m_old;
            #pragma unroll
            for (int t = 0; t < 16; t++) mx = fmaxf(mx, red[tid*17 + t]);
            row_mnew[tid]  = mx;
            row_m[tid]     = mx;
            row_scale[tid] = __expf(m_old - mx);
        }
        __syncthreads();

        #pragma unroll
        for (int i = 0; i < 4; i++) {
            const int r  = ty*4 + i;
            const float mn = row_mnew[r];
            const float sc = row_scale[r];
            float ps = 0.f;
            #pragma unroll
            for (int jj = 0; jj < 4; jj++) {
                const float p = (s[i][jj] < -1e29f) ? 0.f : __expf(s[i][jj] - mn);
                Ps[r*ALD + tx*4 + jj] = p;
                ps += p;
                acc[i][jj] *= sc;
            }
            red[r*17 + tx] = ps;
        }
        __syncthreads();

        if (tid < 64) {
            float sum = 0.f;
            #pragma unroll
            for (int t = 0; t < 16; t++) sum += red[tid*17 + t];
            row_l[tid] = row_l[tid] * row_scale[tid] + sum;
        }

        #pragma unroll 8
        for (int kk = 0; kk < 64; kk++) {
            float p[4], v[4];
            #pragma unroll
            for (int i = 0; i < 4; i++)  p[i] = Ps[(ty*4+i)*ALD + kk];
            #pragma unroll
            for (int jj = 0; jj < 4; jj++) v[jj] = Vs[kk*ALD + tx*4 + jj];
            #pragma unroll
            for (int i = 0; i < 4; i++)
                #pragma unroll
                for (int jj = 0; jj < 4; jj++)
                    acc[i][jj] = fmaf(p[i], v[jj], acc[i][jj]);
        }
        __syncthreads();
    }

    float* ctx = g_ctx + ((size_t)b*S_ + q0)*H_ + h*HD_;
    #pragma unroll
    for (int i = 0; i < 4; i++) {
        const int r = ty*4 + i;
        const float invl = 1.f / row_l[r];
        #pragma unroll
        for (int jj = 0; jj < 4; jj++)
            ctx[(size_t)r*H_ + tx*4 + jj] = acc[i][jj] * invl;
    }
}

// ---------------- launch -----------------------------------------------------
extern "C" void kernel_launch(void* const* d_in, const int* in_sizes, int n_in,
                              void* d_out, int out_size)
{
    const float* x   = (const float*)d_in[0];
    const int*   pos = (const int*)d_in[1];
    const float* wq = (const float*)d_in[2];
    const float* bq = (const float*)d_in[3];
    const float* wk = (const float*)d_in[4];
    const float* bk = (const float*)d_in[5];
    const float* wv = (const float*)d_in[6];
    const float* bv = (const float*)d_in[7];
    const float* wo = (const float*)d_in[8];
    const float* bo = (const float*)d_in[9];
    float* out = (float*)d_out;

    cudaFuncSetAttribute(attn_kernel,
                         cudaFuncAttributeMaxDynamicSharedMemorySize, ATT_SMEM_BYTES);
    cudaFuncSetAttribute(mma_gemm<0>,
                         cudaFuncAttributeMaxDynamicSharedMemorySize, GM_SMEM);
    cudaFuncSetAttribute(mma_gemm<1>,
                         cudaFuncAttributeMaxDynamicSharedMemorySize, GM_SMEM);

    // 1. fp32 -> bf16 hi/lo split (X + 4 weights)
    convert_inputs_kernel<<<(8 << 20) / 256, 256>>>(x, wq, wk, wv, wo);

    // 2. QKV projections (warp MMA)
    dim3 gqkv(H_/128, (B_*S_)/128, 3);
    mma_gemm<0><<<gqkv, 256, GM_SMEM>>>(bq, bk, bv, bo, out);

    // 3. RoPE
    const int npairs = B_*NH_*S_*(HD_/2);
    rope_kernel<<<(npairs + 255)/256, 256>>>(pos);

    // 4. attention
    dim3 gatt(S_/64, NH_, B_);
    attn_kernel<<<gatt, 256, ATT_SMEM_BYTES>>>();

    // 5. ctx -> bf16 split, 6. output projection
    convert_ctx_kernel<<<(4 << 20) / 256, 256>>>();
    dim3 gout(H_/128, (B_*S_)/128, 1);
    mma_gemm<1><<<gout, 256, GM_SMEM>>>(bq, bk, bv, bo, out);
}

// round 17
// speedup vs baseline: 3.5110x; 2.1148x over previous
#include <cuda_runtime.h>
#include <cuda_bf16.h>
#include <math.h>
#include <stdint.h>

#define B_   2
#define S_   2048
#define H_   1024
#define NH_  16
#define HD_  64
#define WIN_ 1024

// ---------------- scratch (device globals: no allocations allowed) ----------
__device__ float g_q[B_*NH_*S_*HD_];
__device__ float g_k[B_*NH_*S_*HD_];
__device__ float g_v[B_*NH_*S_*HD_];
// bf16 split operands (GEMM)
__device__ __nv_bfloat16 g_xh[B_*S_*H_];
__device__ __nv_bfloat16 g_xl[B_*S_*H_];
__device__ __nv_bfloat16 g_wh[4*H_*H_];
__device__ __nv_bfloat16 g_wl[4*H_*H_];
__device__ __nv_bfloat16 g_ch[B_*S_*H_];
__device__ __nv_bfloat16 g_cl[B_*S_*H_];
// bf16 split q/k/v for attention (q pre-scaled by 0.125, rope applied)
__device__ __nv_bfloat16 g_qh[B_*NH_*S_*HD_];
__device__ __nv_bfloat16 g_ql[B_*NH_*S_*HD_];
__device__ __nv_bfloat16 g_kh[B_*NH_*S_*HD_];
__device__ __nv_bfloat16 g_kl[B_*NH_*S_*HD_];
__device__ __nv_bfloat16 g_vh[B_*NH_*S_*HD_];
__device__ __nv_bfloat16 g_vl[B_*NH_*S_*HD_];

// ---------------- helpers (base-target instructions only) --------------------
__device__ __forceinline__ uint32_t smem_u32(const void* p) {
    uint32_t a;
    asm("{ .reg .u64 t; cvta.to.shared.u64 t, %1; cvt.u32.u64 %0, t; }"
        : "=r"(a) : "l"(p));
    return a;
}
__device__ __forceinline__ uint32_t swz(uint32_t o) { return o ^ ((o >> 3) & 0x70); }

__device__ __forceinline__ void cp16(uint32_t dst, const void* src) {
    asm volatile("cp.async.cg.shared.global [%0], [%1], 16;" :: "r"(dst), "l"(src));
}
#define CP_COMMIT() asm volatile("cp.async.commit_group;" ::: "memory")
#define CP_WAIT0()  asm volatile("cp.async.wait_group 0;" ::: "memory")

__device__ __forceinline__ void ldsm_x4(uint32_t& r0, uint32_t& r1,
                                        uint32_t& r2, uint32_t& r3, uint32_t a) {
    asm volatile("ldmatrix.sync.aligned.m8n8.x4.shared.b16 {%0,%1,%2,%3}, [%4];"
                 : "=r"(r0), "=r"(r1), "=r"(r2), "=r"(r3) : "r"(a));
}
__device__ __forceinline__ void ldsm_x4_t(uint32_t& r0, uint32_t& r1,
                                          uint32_t& r2, uint32_t& r3, uint32_t a) {
    asm volatile("ldmatrix.sync.aligned.m8n8.x4.trans.shared.b16 {%0,%1,%2,%3}, [%4];"
                 : "=r"(r0), "=r"(r1), "=r"(r2), "=r"(r3) : "r"(a));
}
__device__ __forceinline__ void mma16816(float* c, const uint32_t* a, const uint32_t* b) {
    asm volatile("mma.sync.aligned.m16n8k16.row.col.f32.bf16.bf16.f32 "
                 "{%0,%1,%2,%3}, {%4,%5,%6,%7}, {%8,%9}, {%0,%1,%2,%3};"
                 : "+f"(c[0]), "+f"(c[1]), "+f"(c[2]), "+f"(c[3])
                 : "r"(a[0]), "r"(a[1]), "r"(a[2]), "r"(a[3]), "r"(b[0]), "r"(b[1]));
}
__device__ __forceinline__ uint32_t packbf(float lo, float hi) {
    uint32_t r;
    asm("cvt.rn.bf16x2.f32 %0, %1, %2;" : "=r"(r) : "f"(hi), "f"(lo));
    return r;
}

// ---------------- conversion kernel -----------------------------------------
__global__ void convert_inputs_kernel(const float* __restrict__ X,
                                      const float* __restrict__ Wq,
                                      const float* __restrict__ Wk,
                                      const float* __restrict__ Wv,
                                      const float* __restrict__ Wo)
{
    const int i = blockIdx.x * 256 + threadIdx.x;
    float v; __nv_bfloat16 *dh, *dl; int off;
    if (i < (1 << 22)) { v = X[i]; dh = g_xh; dl = g_xl; off = i; }
    else {
        const int j = i - (1 << 22);
        const int w = j >> 20;
        const int e = j & ((1 << 20) - 1);
        const float* Ws = (w == 0) ? Wq : (w == 1) ? Wk : (w == 2) ? Wv : Wo;
        v = Ws[e]; dh = g_wh; dl = g_wl; off = (w << 20) + e;
    }
    const __nv_bfloat16 h = __float2bfloat16(v);
    dh[off] = h;
    dl[off] = __float2bfloat16(v - __bfloat162float(h));
}

// ---------------- warp-MMA GEMM (unchanged from R11) -------------------------
#define GM_STAGE (4*16384)
#define GM_SMEM  (2*GM_STAGE + 1024)

template<int MODE>
__global__ __launch_bounds__(256, 1)
void mma_gemm(const float* __restrict__ bq, const float* __restrict__ bk,
              const float* __restrict__ bv, const float* __restrict__ bo,
              float* __restrict__ OUT)
{
    extern __shared__ char smem[];
    const uint32_t sb = smem_u32(smem);
    const uint32_t tile0 = (sb + 1023) & ~1023u;
    const int tid = threadIdx.x, wid = tid >> 5, lid = tid & 31;
    const int wm = wid & 1, wn = wid >> 1;
    const int n0 = blockIdx.x * 128, m0 = blockIdx.y * 128;
    const int z = (MODE == 0) ? (int)blockIdx.z : 3;

    const __nv_bfloat16* Ah = (MODE == 0) ? g_xh : g_ch;
    const __nv_bfloat16* Al = (MODE == 0) ? g_xl : g_cl;
    const __nv_bfloat16* Bh = g_wh + ((size_t)z << 20);
    const __nv_bfloat16* Bl = g_wl + ((size_t)z << 20);
    const float* Bi = (MODE == 0) ? ((z == 0) ? bq : (z == 1) ? bk : bv) : bo;

    const uint32_t stg[2] = { tile0, tile0 + GM_STAGE };

    float acc[4][4][4];
    #pragma unroll
    for (int i = 0; i < 4; i++)
        #pragma unroll
        for (int j = 0; j < 4; j++)
            #pragma unroll
            for (int r = 0; r < 4; r++) acc[i][j][r] = 0.f;

    auto load_chunk = [&](int kc, int buf) {
        const int koff = kc * 64;
        #pragma unroll
        for (int t = 0; t < 16; t++) {
            const int piece  = tid + t * 256;
            const int region = piece >> 10;
            const int rem    = piece & 1023;
            const int row    = rem >> 3;
            const int c16    = rem & 7;
            const uint32_t dst = stg[buf] + region * 16384 + swz(row * 128 + c16 * 16);
            const __nv_bfloat16* src;
            if      (region == 0) src = Ah + (size_t)(m0 + row) * 1024 + koff + c16 * 8;
            else if (region == 1) src = Al + (size_t)(m0 + row) * 1024 + koff + c16 * 8;
            else if (region == 2) src = Bh + (size_t)(n0 + row) * 1024 + koff + c16 * 8;
            else                  src = Bl + (size_t)(n0 + row) * 1024 + koff + c16 * 8;
            cp16(dst, src);
        }
        CP_COMMIT();
    };

    const int a_row = lid & 15, a_k16 = lid >> 4;
    const int b_row = (lid & 7) + ((lid >> 4) & 1) * 8;
    const int b_k16 = (lid >> 3) & 1;

    load_chunk(0, 0);

    for (int c = 0; c < 16; c++) {
        const int cur = c & 1;
        CP_WAIT0();
        __syncthreads();
        if (c + 1 < 16) load_chunk(c + 1, cur ^ 1);

        const uint32_t ahB = stg[cur];
        const uint32_t alB = stg[cur] + 16384;
        const uint32_t bhB = stg[cur] + 32768;
        const uint32_t blB = stg[cur] + 49152;

        #pragma unroll
        for (int s = 0; s < 4; s++) {
            uint32_t ah[4][4], al[4][4], bh[2][4], bl[2][4];
            #pragma unroll
            for (int mf = 0; mf < 4; mf++) {
                const uint32_t off = swz((wm*64 + mf*16 + a_row) * 128 + s*32 + a_k16*16);
                ldsm_x4(ah[mf][0], ah[mf][1], ah[mf][2], ah[mf][3], ahB + off);
                ldsm_x4(al[mf][0], al[mf][1], al[mf][2], al[mf][3], alB + off);
            }
            #pragma unroll
            for (int np = 0; np < 2; np++) {
                const uint32_t off = swz((wn*32 + np*16 + b_row) * 128 + s*32 + b_k16*16);
                ldsm_x4(bh[np][0], bh[np][1], bh[np][2], bh[np][3], bhB + off);
                ldsm_x4(bl[np][0], bl[np][1], bl[np][2], bl[np][3], blB + off);
            }
            #pragma unroll
            for (int mf = 0; mf < 4; mf++)
                #pragma unroll
                for (int nf = 0; nf < 4; nf++) {
                    const uint32_t* bhf = &bh[nf >> 1][(nf & 1) * 2];
                    const uint32_t* blf = &bl[nf >> 1][(nf & 1) * 2];
                    mma16816(acc[mf][nf], ah[mf], bhf);
                    mma16816(acc[mf][nf], ah[mf], blf);
                    mma16816(acc[mf][nf], al[mf], bhf);
                }
        }
        __syncthreads();
    }

    const int erow = lid >> 2, ecol = (lid & 3) * 2;
    #pragma unroll
    for (int mf = 0; mf < 4; mf++) {
        #pragma unroll
        for (int nf = 0; nf < 4; nf++) {
            const int n  = n0 + wn*32 + nf*8 + ecol;
            const float bias0 = Bi[n], bias1 = Bi[n + 1];
            #pragma unroll
            for (int half = 0; half < 2; half++) {
                const int m = m0 + wm*64 + mf*16 + erow + half*8;
                const float v0 = acc[mf][nf][half*2 + 0] + bias0;
                const float v1 = acc[mf][nf][half*2 + 1] + bias1;
                if (MODE == 0) {
                    const int b = m >> 11;
                    const int s = m & (S_ - 1);
                    const int h = n >> 6;
                    const int d = n & 63;
                    float* dst = ((z == 0) ? g_q : (z == 1) ? g_k : g_v)
                               + (((size_t)b * NH_ + h) * S_ + s) * HD_ + d;
                    *(float2*)dst = make_float2(v0, v1);
                } else {
                    *(float2*)(OUT + (size_t)m * H_ + n) = make_float2(v0, v1);
                }
            }
        }
    }
}

// ---------------- RoPE + bf16 hi/lo convert (q scaled by 0.125) --------------
__global__ void rope_convert_kernel(const int* __restrict__ pos32)
{
    const int idx = blockIdx.x * blockDim.x + threadIdx.x;
    if (idx >= B_*NH_*S_*(HD_/2)) return;
    const int d  = idx & 31;
    const int t  = idx >> 5;
    const int s  = t & (S_ - 1);
    const int t2 = t >> 11;
    const int h  = t2 & (NH_ - 1);
    const int b  = t2 >> 4;

    const bool is64 = (pos32[1] == 0) && (pos32[2] == 1) && (pos32[3] == 0);
    const int pidx = b*S_ + s;
    int p = is64 ? pos32[2*pidx] : pos32[pidx];
    if (p < 0) p = 0;
    if (p > 2047) p = 2047;

    const float inv = expf(-0.28782313662425575f * (float)d);
    const float ang = (float)p * inv;
    float sn, cs;
    sincosf(ang, &sn, &cs);

    const size_t base = (((size_t)b*NH_ + h)*S_ + s)*HD_;
    // q: rope + 0.125 scale, split
    const float q1 = g_q[base + d], q2 = g_q[base + d + 32];
    const float qa = (q1*cs - q2*sn) * 0.125f;
    const float qb = (q2*cs + q1*sn) * 0.125f;
    __nv_bfloat16 ha = __float2bfloat16(qa);
    __nv_bfloat16 hb = __float2bfloat16(qb);
    g_qh[base + d]      = ha; g_ql[base + d]      = __float2bfloat16(qa - __bfloat162float(ha));
    g_qh[base + d + 32] = hb; g_ql[base + d + 32] = __float2bfloat16(qb - __bfloat162float(hb));
    // k: rope, split
    const float k1 = g_k[base + d], k2 = g_k[base + d + 32];
    const float ka = k1*cs - k2*sn;
    const float kb = k2*cs + k1*sn;
    ha = __float2bfloat16(ka); hb = __float2bfloat16(kb);
    g_kh[base + d]      = ha; g_kl[base + d]      = __float2bfloat16(ka - __bfloat162float(ha));
    g_kh[base + d + 32] = hb; g_kl[base + d + 32] = __float2bfloat16(kb - __bfloat162float(hb));
    // v: split
    const float v1 = g_v[base + d], v2 = g_v[base + d + 32];
    ha = __float2bfloat16(v1); hb = __float2bfloat16(v2);
    g_vh[base + d]      = ha; g_vl[base + d]      = __float2bfloat16(v1 - __bfloat162float(ha));
    g_vh[base + d + 32] = hb; g_vl[base + d + 32] = __float2bfloat16(v2 - __bfloat162float(hb));
}

// ---------------- tensor-core flash attention --------------------------------
// Block = 128 q rows (8 warps x m16), full head. KV tiles of 64 keys,
// double-buffered. S and O via mma.sync bf16 hi/lo split. P stays in regs.
// Epilogue writes ctx directly as bf16 hi/lo (feeds out-proj GEMM).
#define AT_SMEM (1024 + 32768 + 2*32768)

__global__ __launch_bounds__(256)
void attn_mma_kernel()
{
    extern __shared__ char smem[];
    const uint32_t sb = (smem_u32(smem) + 1023) & ~1023u;
    const int tid = threadIdx.x, wid = tid >> 5, lid = tid & 31;
    const int qi = blockIdx.x, h = blockIdx.y, b = blockIdx.z;
    const int q0 = qi * 128;
    const size_t bh = (size_t)b*NH_ + h;
    const size_t gbase = bh * S_ * 64;

    const uint32_t sQH = sb, sQL = sb + 16384;
    const uint32_t stg[2] = { sb + 32768, sb + 65536 };

    // load Q (128 rows x 128B, hi+lo)
    #pragma unroll
    for (int t = 0; t < 8; t++) {
        const int p = tid + t*256;
        const int rg = p >> 10, rem = p & 1023, row = rem >> 3, c16 = rem & 7;
        const __nv_bfloat16* src = (rg ? g_ql : g_qh) + gbase + (size_t)(q0 + row)*64 + c16*8;
        cp16((rg ? sQL : sQH) + swz(row*128 + c16*16), src);
    }
    CP_COMMIT();

    int j0 = q0 - WIN_ + 1; j0 = (j0 < 0) ? 0 : (j0 >> 6);
    const int jmax = (q0 + 127) >> 6;

    auto load_kv = [&](int j, int st) {
        const int k0 = j * 64;
        #pragma unroll
        for (int t = 0; t < 8; t++) {
            const int p = tid + t*256;
            const int rg = p >> 9, rem = p & 511, row = rem >> 3, c16 = rem & 7;
            const __nv_bfloat16* base =
                (rg == 0) ? g_kh : (rg == 1) ? g_kl : (rg == 2) ? g_vh : g_vl;
            cp16(stg[st] + rg*8192 + swz(row*128 + c16*16),
                 base + gbase + (size_t)(k0 + row)*64 + c16*8);
        }
        CP_COMMIT();
    };

    load_kv(j0, 0);

    float O[8][4];
    #pragma unroll
    for (int i = 0; i < 8; i++)
        #pragma unroll
        for (int r = 0; r < 4; r++) O[i][r] = 0.f;
    float m0p = -1e30f, m1p = -1e30f, l0 = 0.f, l1 = 0.f;

    const int a_row = lid & 15, a_kh = lid >> 4;
    const int b_row = (lid & 7) + ((lid >> 4) & 1) * 8, b_k16 = (lid >> 3) & 1;
    const int v_row = lid & 15, v_ch = (lid >> 4) & 1;
    const int r0g = q0 + wid*16 + (lid >> 2);
    const int r1g = r0g + 8;

    for (int j = j0; j <= jmax; j++) {
        const int st = (j - j0) & 1;
        CP_WAIT0();
        __syncthreads();
        if (j + 1 <= jmax) load_kv(j + 1, st ^ 1);

        const uint32_t KH = stg[st], KL = KH + 8192, VH = KH + 16384, VL = KH + 24576;
        const int k0 = j * 64;

        // ---- S = Qh Kh + Qh Kl + Ql Kh ----
        float S[8][4];
        #pragma unroll
        for (int i = 0; i < 8; i++)
            #pragma unroll
            for (int r = 0; r < 4; r++) S[i][r] = 0.f;

        #pragma unroll
        for (int s = 0; s < 4; s++) {
            uint32_t ah[4], al[4];
            const uint32_t qoff = swz((wid*16 + a_row)*128 + s*32 + a_kh*16);
            ldsm_x4(ah[0], ah[1], ah[2], ah[3], sQH + qoff);
            ldsm_x4(al[0], al[1], al[2], al[3], sQL + qoff);
            uint32_t kh4[4][4], kl4[4][4];
            #pragma unroll
            for (int g = 0; g < 4; g++) {
                const uint32_t koff = swz((g*16 + b_row)*128 + s*32 + b_k16*16);
                ldsm_x4(kh4[g][0], kh4[g][1], kh4[g][2], kh4[g][3], KH + koff);
                ldsm_x4(kl4[g][0], kl4[g][1], kl4[g][2], kl4[g][3], KL + koff);
            }
            #pragma unroll
            for (int nf = 0; nf < 8; nf++) {
                const uint32_t* bhf = &kh4[nf >> 1][(nf & 1) * 2];
                const uint32_t* blf = &kl4[nf >> 1][(nf & 1) * 2];
                mma16816(S[nf], ah, bhf);
                mma16816(S[nf], ah, blf);
                mma16816(S[nf], al, bhf);
            }
        }

        // ---- mask ----
        #pragma unroll
        for (int nf = 0; nf < 8; nf++) {
            #pragma unroll
            for (int ci = 0; ci < 2; ci++) {
                const int col = k0 + nf*8 + (lid & 3)*2 + ci;
                if (col > r0g || r0g - col >= WIN_) S[nf][ci]     = -1e30f;
                if (col > r1g || r1g - col >= WIN_) S[nf][2 + ci] = -1e30f;
            }
        }

        // ---- online softmax (register + shuffle) ----
        float mc0 = -1e30f, mc1 = -1e30f;
        #pragma unroll
        for (int nf = 0; nf < 8; nf++) {
            mc0 = fmaxf(mc0, fmaxf(S[nf][0], S[nf][1]));
            mc1 = fmaxf(mc1, fmaxf(S[nf][2], S[nf][3]));
        }
        mc0 = fmaxf(mc0, __shfl_xor_sync(0xFFFFFFFFu, mc0, 1));
        mc0 = fmaxf(mc0, __shfl_xor_sync(0xFFFFFFFFu, mc0, 2));
        mc1 = fmaxf(mc1, __shfl_xor_sync(0xFFFFFFFFu, mc1, 1));
        mc1 = fmaxf(mc1, __shfl_xor_sync(0xFFFFFFFFu, mc1, 2));
        const float mn0 = fmaxf(m0p, mc0), mn1 = fmaxf(m1p, mc1);
        const float sc0 = __expf(m0p - mn0), sc1 = __expf(m1p - mn1);
        m0p = mn0; m1p = mn1;

        float ps0 = 0.f, ps1 = 0.f;
        #pragma unroll
        for (int nf = 0; nf < 8; nf++) {
            S[nf][0] = (S[nf][0] < -1e29f) ? 0.f : __expf(S[nf][0] - mn0);
            S[nf][1] = (S[nf][1] < -1e29f) ? 0.f : __expf(S[nf][1] - mn0);
            S[nf][2] = (S[nf][2] < -1e29f) ? 0.f : __expf(S[nf][2] - mn1);
            S[nf][3] = (S[nf][3] < -1e29f) ? 0.f : __expf(S[nf][3] - mn1);
            ps0 += S[nf][0] + S[nf][1];
            ps1 += S[nf][2] + S[nf][3];
        }
        ps0 += __shfl_xor_sync(0xFFFFFFFFu, ps0, 1);
        ps0 += __shfl_xor_sync(0xFFFFFFFFu, ps0, 2);
        ps1 += __shfl_xor_sync(0xFFFFFFFFu, ps1, 1);
        ps1 += __shfl_xor_sync(0xFFFFFFFFu, ps1, 2);
        l0 = l0 * sc0 + ps0;
        l1 = l1 * sc1 + ps1;
        #pragma unroll
        for (int df = 0; df < 8; df++) {
            O[df][0] *= sc0; O[df][1] *= sc0;
            O[df][2] *= sc1; O[df][3] *= sc1;
        }

        // ---- O += Ph Vh + Ph Vl + Pl Vh ----
        #pragma unroll
        for (int kk = 0; kk < 4; kk++) {
            const float* s0 = S[2*kk];
            const float* s1 = S[2*kk + 1];
            float hf[8], lf[8];
            #pragma unroll
            for (int e = 0; e < 4; e++) {
                hf[e]     = __bfloat162float(__float2bfloat16(s0[e]));
                lf[e]     = s0[e] - hf[e];
                hf[4 + e] = __bfloat162float(__float2bfloat16(s1[e]));
                lf[4 + e] = s1[e] - hf[4 + e];
            }
            uint32_t pah[4], pal[4];
            pah[0] = packbf(hf[0], hf[1]); pah[1] = packbf(hf[2], hf[3]);
            pah[2] = packbf(hf[4], hf[5]); pah[3] = packbf(hf[6], hf[7]);
            pal[0] = packbf(lf[0], lf[1]); pal[1] = packbf(lf[2], lf[3]);
            pal[2] = packbf(lf[4], lf[5]); pal[3] = packbf(lf[6], lf[7]);

            uint32_t vh4[4][4], vl4[4][4];
            #pragma unroll
            for (int dg = 0; dg < 4; dg++) {
                const uint32_t voff = swz((kk*16 + v_row)*128 + dg*32 + v_ch*16);
                ldsm_x4_t(vh4[dg][0], vh4[dg][1], vh4[dg][2], vh4[dg][3], VH + voff);
                ldsm_x4_t(vl4[dg][0], vl4[dg][1], vl4[dg][2], vl4[dg][3], VL + voff);
            }
            #pragma unroll
            for (int df = 0; df < 8; df++) {
                const uint32_t* bhf = &vh4[df >> 1][(df & 1) * 2];
                const uint32_t* blf = &vl4[df >> 1][(df & 1) * 2];
                mma16816(O[df], pah, bhf);
                mma16816(O[df], pah, blf);
                mma16816(O[df], pal, bhf);
            }
        }
        __syncthreads();
    }

    // ---- epilogue: write ctx directly as bf16 hi/lo split (packed stores) ----
    const float i0 = 1.f / l0, i1 = 1.f / l1;
    const size_t c0base = ((size_t)b*S_ + r0g)*H_ + h*64;
    const size_t c1base = ((size_t)b*S_ + r1g)*H_ + h*64;
    #pragma unroll
    for (int df = 0; df < 8; df++) {
        const int d = df*8 + (lid & 3)*2;
        // row 0
        {
            const float v0 = O[df][0]*i0, v1 = O[df][1]*i0;
            const float h0 = __bfloat162float(__float2bfloat16(v0));
            const float h1 = __bfloat162float(__float2bfloat16(v1));
            *(uint32_t*)&g_ch[c0base + d] = packbf(h0, h1);
            *(uint32_t*)&g_cl[c0base + d] = packbf(v0 - h0, v1 - h1);
        }
        // row 1
        {
            const float v0 = O[df][2]*i1, v1 = O[df][3]*i1;
            const float h0 = __bfloat162float(__float2bfloat16(v0));
            const float h1 = __bfloat162float(__float2bfloat16(v1));
            *(uint32_t*)&g_ch[c1base + d] = packbf(h0, h1);
            *(uint32_t*)&g_cl[c1base + d] = packbf(v0 - h0, v1 - h1);
        }
    }
}

// ---------------- launch -----------------------------------------------------
extern "C" void kernel_launch(void* const* d_in, const int* in_sizes, int n_in,
                              void* d_out, int out_size)
{
    const float* x   = (const float*)d_in[0];
    const int*   pos = (const int*)d_in[1];
    const float* wq = (const float*)d_in[2];
    const float* bq = (const float*)d_in[3];
    const float* wk = (const float*)d_in[4];
    const float* bk = (const float*)d_in[5];
    const float* wv = (const float*)d_in[6];
    const float* bv = (const float*)d_in[7];
    const float* wo = (const float*)d_in[8];
    const float* bo = (const float*)d_in[9];
    float* out = (float*)d_out;

    cudaFuncSetAttribute(mma_gemm<0>,
                         cudaFuncAttributeMaxDynamicSharedMemorySize, GM_SMEM);
    cudaFuncSetAttribute(mma_gemm<1>,
                         cudaFuncAttributeMaxDynamicSharedMemorySize, GM_SMEM);
    cudaFuncSetAttribute(attn_mma_kernel,
                         cudaFuncAttributeMaxDynamicSharedMemorySize, AT_SMEM);

    // 1. fp32 -> bf16 hi/lo split (X + 4 weights)
    convert_inputs_kernel<<<(8 << 20) / 256, 256>>>(x, wq, wk, wv, wo);

    // 2. QKV projections (warp MMA)
    dim3 gqkv(H_/128, (B_*S_)/128, 3);
    mma_gemm<0><<<gqkv, 256, GM_SMEM>>>(bq, bk, bv, bo, out);

    // 3. RoPE + hi/lo bf16 conversion of q/k/v
    const int npairs = B_*NH_*S_*(HD_/2);
    rope_convert_kernel<<<(npairs + 255)/256, 256>>>(pos);

    // 4. tensor-core flash attention (writes bf16 ctx split directly)
    dim3 gatt(S_/128, NH_, B_);
    attn_mma_kernel<<<gatt, 256, AT_SMEM>>>();

    // 5. output projection
    dim3 gout(H_/128, (B_*S_)/128, 1);
    mma_gemm<1><<<gout, 256, GM_SMEM>>>(bq, bk, bv, bo, out);
}